// round 9
// baseline (speedup 1.0000x reference)
#include <cuda_runtime.h>
#include <math.h>

#define NB 32
#define NH 512
#define NW 512
#define NM 96
#define NCo 263
#define SW 264
#define RANKSEL 105334u   // 0-based median rank incl. 1581 pad zeros per plane
#define CAP 207872

__constant__ float RL[16] = {
  0.05441584224308161f,   0.3128715909144659f,    0.6756307362980128f,
  0.5853546836548691f,   -0.015829105256023893f, -0.2840155429624281f,
  0.00047248457399797254f,0.128747426620186f,    -0.01736930100202211f,
 -0.04408825393106472f,   0.013981027917015516f,  0.008746094047015655f,
 -0.00487035299301066f,  -0.0003917403729959771f, 0.0006754494059985568f,
 -0.00011747678400228192f
};

__device__ float g_lo[(size_t)NM*NH*SW];   // scratch: rl after inv_cols
__device__ float g_hi[(size_t)NM*NH*SW];   // scratch: rh after inv_cols
__device__ float g_ll[(size_t)NM*SW*SW];   // layout [m][jh][w]
__device__ float g_lh[(size_t)NM*SW*SW];
__device__ float g_hl[(size_t)NM*SW*SW];
__device__ float g_hh[(size_t)NM*SW*SW];
__device__ float g_thr[NM];
__device__ unsigned g_hist0[NM*2048];
__device__ unsigned g_hist1[NM*2048];
__device__ unsigned g_ccnt[NM];
__device__ unsigned g_pref0[NM];
__device__ unsigned g_rank1[NM];
__device__ unsigned g_cand[(size_t)NM*CAP];

__device__ __forceinline__ int refl(int q, int n) {
  q = (q < 0) ? (-q - 1) : q;
  return (q >= n) ? (2*n - 1 - q) : q;
}
__device__ __forceinline__ float softf(float c, float t) {
  float a = fabsf(c) - t;
  return (a > 0.f) ? copysignf(a, c) : 0.f;
}
__device__ __forceinline__ void hadd(unsigned* h, unsigned bin) {
  unsigned mk = __match_any_sync(__activemask(), bin);
  int lane = threadIdx.x & 31;
  if ((__ffs(mk) - 1) == lane) atomicAdd(&h[bin], (unsigned)__popc(mk));
}

template<int NT, int K>
__device__ void select_bin(const unsigned* hist, unsigned rank,
                           unsigned* s_bin, unsigned* s_rem) {
  __shared__ unsigned wtot[NT/32];
  int tid = threadIdx.x, lane = tid & 31, wid = tid >> 5;
  unsigned tsum = 0;
  #pragma unroll
  for (int k = 0; k < K; k++) tsum += hist[tid*K + k];
  unsigned v = tsum;
  #pragma unroll
  for (int o = 1; o < 32; o <<= 1) {
    unsigned n = __shfl_up_sync(0xffffffffu, v, o);
    if (lane >= o) v += n;
  }
  if (lane == 31) wtot[wid] = v;
  __syncthreads();
  if (tid == 0) {
    unsigned s = 0;
    for (int w = 0; w < NT/32; w++) { unsigned t = wtot[w]; wtot[w] = s; s += t; }
  }
  __syncthreads();
  unsigned incl = v + wtot[wid];
  unsigned excl = incl - tsum;
  if (rank >= excl && rank < incl) {
    unsigned c = excl;
    #pragma unroll
    for (int k = 0; k < K; k++) {
      unsigned hb = hist[tid*K + k];
      if (rank < c + hb) { *s_bin = (unsigned)(tid*K + k); *s_rem = rank - c; break; }
      c += hb;
    }
  }
  __syncthreads();
}

__global__ void k_zero() {
  int i = blockIdx.x*256 + threadIdx.x;
  if (i < NM*2048) { g_hist0[i] = 0u; g_hist1[i] = 0u; }
  if (i < NM) g_ccnt[i] = 0u;
}

// ---- FUSED forward: x -> row DWT (smem) -> col DWT -> 4 subbands + hist ----
// block: (w-tile of 16 coeffs, jh-chunk of <=9 groups) x plane m
__global__ void __launch_bounds__(256) k_fwd(const float* __restrict__ x) {
  __shared__ float xs[86*47];
  __shared__ float ls[86*17], hs[86*17];
  __shared__ unsigned hist[2048];
  int bx = blockIdx.x;
  int wt = bx % 17, jc = bx / 17;
  int m = blockIdx.y;
  int b = m / 3, c = m - 3*b;
  int w0 = wt*16;
  int g0 = 9*jc, ge = min(g0 + 8, 65), ng = ge - g0 + 1;
  int nrows = 8*(ng - 1) + 22;
  int hq0 = 8*g0 - 14;
  int wq0 = 2*w0 - 14;
  int tid = threadIdx.x;
  for (int i = tid; i < 2048; i += 256) hist[i] = 0u;
  // load reflected x window (scalar NHWC reads; cross-channel overlap hits L2)
  for (int idx = tid; idx < nrows*46; idx += 256) {
    int r = idx / 46, col = idx - 46*r;
    int hr = refl(hq0 + r, NH);
    int wc = refl(wq0 + col, NW);
    xs[r*47 + col] = x[((size_t)(b*NH + hr)*NW + wc)*3 + c];
  }
  __syncthreads();
  // phase 1: row DWT -> ls/hs
  for (int tt = tid; tt < nrows*4; tt += 256) {
    int r = tt >> 2, grp = tt & 3;
    const float* xr = xs + r*47 + 8*grp;
    float samp[22];
    #pragma unroll
    for (int k = 0; k < 22; k++) samp[k] = xr[k];
    #pragma unroll
    for (int e = 0; e < 4; e++) {
      float av = 0.f, dv = 0.f;
      #pragma unroll
      for (int i = 0; i < 16; i++) {
        float v = samp[2*e + i];
        av += RL[i] * v;
        dv += ((i & 1) ? -RL[15-i] : RL[15-i]) * v;
      }
      ls[r*17 + 4*grp + e] = av;
      hs[r*17 + 4*grp + e] = dv;
    }
  }
  __syncthreads();
  // phase 2: column DWT -> subbands [m][jh][w] + histogram of details
  if (tid < 16*ng) {
    int wl = tid & 15, gl = tid >> 4;
    int g = g0 + gl;
    int w = w0 + wl;
    bool wv = (w < SW), wr = (w < NCo);
    size_t mb = (size_t)m*SW*SW;
    #pragma unroll
    for (int z = 0; z < 2; z++) {
      const float* src = (z ? hs : ls) + wl;
      float samp[22];
      #pragma unroll
      for (int k = 0; k < 22; k++) samp[k] = src[(8*gl + k)*17];
      float a[4], d[4];
      #pragma unroll
      for (int r = 0; r < 4; r++) {
        float av = 0.f, dv = 0.f;
        #pragma unroll
        for (int i = 0; i < 16; i++) {
          float v = samp[2*r + i];
          av += RL[i] * v;
          dv += ((i & 1) ? -RL[15-i] : RL[15-i]) * v;
        }
        a[r] = av; d[r] = dv;
      }
      float* oa = (z ? g_hl : g_ll) + mb;
      float* od = (z ? g_hh : g_lh) + mb;
      #pragma unroll
      for (int r = 0; r < 4; r++) {
        int jh = 4*g + r;
        float av = wr ? a[r] : 0.f;
        float dv = wr ? d[r] : 0.f;
        if (jh == 263) { av = 0.f; dv = 0.f; }
        if (wv) {
          oa[(size_t)jh*SW + w] = av;
          od[(size_t)jh*SW + w] = dv;
          hadd(hist, __float_as_uint(fabsf(dv)) >> 21);
          if (z) hadd(hist, __float_as_uint(fabsf(av)) >> 21);
        }
      }
    }
  }
  __syncthreads();
  for (int i = tid; i < 2048; i += 256)
    if (hist[i]) atomicAdd(&g_hist0[m*2048 + i], hist[i]);
}

// ---- M2: per-block redundant pass-0 select + refine hist + compact keys ----
__global__ void __launch_bounds__(256) k_pass1() {
  __shared__ unsigned hist[2048];
  __shared__ unsigned s_bin, s_rem;
  int cx = blockIdx.x, m = blockIdx.y, band = blockIdx.z;
  select_bin<256, 8>(g_hist0 + m*2048, RANKSEL, &s_bin, &s_rem);
  unsigned pref0 = s_bin;
  if (cx == 0 && band == 0 && threadIdx.x == 0) {
    g_pref0[m] = s_bin; g_rank1[m] = s_rem;
  }
  const float* bp = (band == 0 ? g_lh : (band == 1 ? g_hl : g_hh)) + (size_t)m*SW*SW;
  const float4* p = (const float4*)bp;
  for (int i = threadIdx.x; i < 2048; i += 256) hist[i] = 0u;
  __syncthreads();
  int lo = cx*2178, hi = lo + 2178;
  int lane = threadIdx.x & 31;
  for (int base = lo; base < hi; base += 256) {
    int i = base + threadIdx.x;
    float4 v = make_float4(0.f, 0.f, 0.f, 0.f);
    if (i < hi) v = p[i];
    #pragma unroll
    for (int e = 0; e < 4; e++) {
      unsigned key = __float_as_uint(fabsf((&v.x)[e]));
      bool ok = (i < hi) && ((key >> 21) == pref0);
      unsigned mk = __ballot_sync(0xffffffffu, ok);
      if (mk) {
        int leader = __ffs(mk) - 1;
        unsigned basec = 0;
        if (lane == leader) basec = atomicAdd(&g_ccnt[m], (unsigned)__popc(mk));
        basec = __shfl_sync(0xffffffffu, basec, leader);
        if (ok) {
          atomicAdd(&hist[(key >> 10) & 2047u], 1u);
          g_cand[(size_t)m*CAP + basec + __popc(mk & ((1u << lane) - 1u))] = key;
        }
      }
    }
  }
  __syncthreads();
  for (int i = threadIdx.x; i < 2048; i += 256)
    if (hist[i]) atomicAdd(&g_hist1[m*2048 + i], hist[i]);
}

// ---- M3: finish on candidates -> threshold ---------------------------------
__global__ void __launch_bounds__(512) k_final() {
  int m = blockIdx.x;
  __shared__ unsigned sh[2048];
  __shared__ unsigned s_bin, s_rem;
  for (int i = threadIdx.x; i < 2048; i += 512) sh[i] = g_hist1[m*2048 + i];
  __syncthreads();
  select_bin<512, 4>(sh, g_rank1[m], &s_bin, &s_rem);
  unsigned pref01 = (g_pref0[m] << 11) | s_bin;
  unsigned r2 = s_rem;
  __syncthreads();
  for (int i = threadIdx.x; i < 1024; i += 512) sh[i] = 0u;
  __syncthreads();
  unsigned cnt = g_ccnt[m];
  const unsigned* cand = g_cand + (size_t)m*CAP;
  for (unsigned i = threadIdx.x; i < cnt; i += 512) {
    unsigned key = cand[i];
    if ((key >> 10) == pref01) atomicAdd(&sh[key & 1023u], 1u);
  }
  __syncthreads();
  select_bin<512, 2>(sh, r2, &s_bin, &s_rem);
  if (threadIdx.x == 0) {
    unsigned key = (pref01 << 10) | s_bin;
    double med = (double)__uint_as_float(key);
    g_thr[m] = (float)(med / 0.6745 * sqrt(2.0 * log(262144.0)));
  }
}

// ---- C: inverse column DWT (subbands [jh][w]), soft fused ------------------
__global__ void __launch_bounds__(256) k_inv_cols() {
  __shared__ float ca[32*71], cd[32*71];
  int bx = blockIdx.x, wt = bx % 9, jc = bx / 9;
  int m = blockIdx.y, z = blockIdx.z;
  int w0 = wt*32, gc0 = 16*jc, p_lo = 64*jc;
  const float* A = (z ? g_hl : g_ll) + (size_t)m*SW*SW;
  const float* D = (z ? g_hh : g_lh) + (size_t)m*SW*SW;
  float* out = (z ? g_hi : g_lo) + (size_t)m*NH*SW;
  float thr = g_thr[m];
  for (int idx = threadIdx.x; idx < 32*71; idx += 256) {
    int wl = idx & 31, rr = idx >> 5;
    int w = w0 + wl, p = p_lo + rr;
    float va = 0.f, vd = 0.f;
    if (w < NCo) { va = A[(size_t)p*SW + w]; vd = D[(size_t)p*SW + w]; }
    if (z) va = softf(va, thr);
    vd = softf(vd, thr);
    ca[wl*71 + rr] = va;
    cd[wl*71 + rr] = vd;
  }
  __syncthreads();
  int lane = threadIdx.x & 31, warp = threadIdx.x >> 5;
  int w = w0 + lane;
  bool wok = (w < NCo);
  const float* cap = ca + lane*71;
  const float* cdp = cd + lane*71;
  for (int gl = warp; gl < 16; gl += 8) {
    int gc = gc0 + gl, pr = 4*gl;
    float ac[11], dc[11];
    #pragma unroll
    for (int k = 0; k < 11; k++) { ac[k] = cap[pr + k]; dc[k] = cdp[pr + k]; }
    #pragma unroll
    for (int r = 0; r < 4; r++) {
      float y0 = 0.f, y1 = 0.f;
      #pragma unroll
      for (int u = 0; u < 8; u++) {
        float va = ac[r + 7 - u], vd = dc[r + 7 - u];
        y0 += va * RL[2*u]     + vd * RL[15 - 2*u];
        y1 += va * RL[2*u + 1] - vd * RL[14 - 2*u];
      }
      if (wok) {
        int i0 = 8*gc + 2*r;
        out[(size_t)i0*SW + w]     = y0;
        out[(size_t)(i0+1)*SW + w] = y1;
      }
    }
  }
}

// ---- D: inverse row DWT + NHWC interleave, 2 rows/block --------------------
__global__ void __launch_bounds__(256) k_inv_rows(float* __restrict__ out) {
  __shared__ float ca[2][888], cd[2][888], rowbuf[2][1536];
  int h0 = blockIdx.x*2, b = blockIdx.y;
  for (int i = threadIdx.x; i < 396; i += 256) {
    int rr = i / 198, t2 = i - 198*rr;
    int c = t2 / 66, f = t2 - 66*c;
    const float4* rl4 = (const float4*)(g_lo + ((size_t)(b*3 + c)*NH + h0 + rr)*SW);
    const float4* rh4 = (const float4*)(g_hi + ((size_t)(b*3 + c)*NH + h0 + rr)*SW);
    float4 va = rl4[f], vd = rh4[f];
    int a0 = c*296 + 4*f + (f >> 1);
    #pragma unroll
    for (int e = 0; e < 4; e++) { ca[rr][a0 + e] = (&va.x)[e]; cd[rr][a0 + e] = (&vd.x)[e]; }
  }
  __syncthreads();
  for (int t = threadIdx.x; t < 384; t += 256) {
    int rr = t / 192, rem = t - 192*rr;
    int c = rem >> 6, gc = rem & 63, p0 = 4*gc;
    float ac[11], dc[11];
    #pragma unroll
    for (int k = 0; k < 11; k++) {
      int p = p0 + k, a = c*296 + p + (p >> 3);
      ac[k] = ca[rr][a]; dc[k] = cd[rr][a];
    }
    #pragma unroll
    for (int r = 0; r < 4; r++) {
      float y0 = 0.f, y1 = 0.f;
      #pragma unroll
      for (int u = 0; u < 8; u++) {
        float va = ac[r + 7 - u], vd = dc[r + 7 - u];
        y0 += va * RL[2*u]     + vd * RL[15 - 2*u];
        y1 += va * RL[2*u + 1] - vd * RL[14 - 2*u];
      }
      int o = 2*(p0 + r);
      rowbuf[rr][o*3 + c]       = y0;
      rowbuf[rr][(o + 1)*3 + c] = y1;
    }
  }
  __syncthreads();
  float4* orow = (float4*)(out + (size_t)(b*NH + h0)*NW*3);
  const float4* rb = (const float4*)rowbuf;
  for (int i = threadIdx.x; i < 768; i += 256) orow[i] = rb[i];
}

extern "C" void kernel_launch(void* const* d_in, const int* in_sizes, int n_in,
                              void* d_out, int out_size) {
  const float* x = (const float*)d_in[0];
  float* out = (float*)d_out;
  k_zero<<<(NM*2048 + 255)/256, 256>>>();
  k_fwd<<<dim3(136, NM), 256>>>(x);
  k_pass1<<<dim3(8, NM, 3), 256>>>();
  k_final<<<NM, 512>>>();
  k_inv_cols<<<dim3(36, NM, 2), 256>>>();
  k_inv_rows<<<dim3(NH/2, NB), 256>>>(out);
}

// round 10
// speedup vs baseline: 1.0058x; 1.0058x over previous
#include <cuda_runtime.h>
#include <math.h>

#define NB 32
#define NH 512
#define NW 512
#define NM 96
#define NCo 263
#define SW 264
#define RANKSEL 105334u   // 0-based median rank incl. 1581 pad zeros per plane
#define CAP 207872

__constant__ float RL[16] = {
  0.05441584224308161f,   0.3128715909144659f,    0.6756307362980128f,
  0.5853546836548691f,   -0.015829105256023893f, -0.2840155429624281f,
  0.00047248457399797254f,0.128747426620186f,    -0.01736930100202211f,
 -0.04408825393106472f,   0.013981027917015516f,  0.008746094047015655f,
 -0.00487035299301066f,  -0.0003917403729959771f, 0.0006754494059985568f,
 -0.00011747678400228192f
};

__device__ float g_lo[(size_t)NM*NH*SW];   // [m][h][w-coeff]; rl after inv_cols
__device__ float g_hi[(size_t)NM*NH*SW];
__device__ float g_ll[(size_t)NM*SW*SW];   // subbands: layout [m][jh][w]
__device__ float g_lh[(size_t)NM*SW*SW];
__device__ float g_hl[(size_t)NM*SW*SW];
__device__ float g_hh[(size_t)NM*SW*SW];
__device__ float g_thr[NM];
__device__ unsigned g_hist0[NM*2048];
__device__ unsigned g_hist1[NM*2048];
__device__ unsigned g_ccnt[NM];
__device__ unsigned g_pref0[NM];
__device__ unsigned g_rank1[NM];
__device__ unsigned g_cand[(size_t)NM*CAP];

__device__ __forceinline__ int refl(int q, int n) {
  q = (q < 0) ? (-q - 1) : q;
  return (q >= n) ? (2*n - 1 - q) : q;
}
__device__ __forceinline__ float softf(float c, float t) {
  float a = fabsf(c) - t;
  return (a > 0.f) ? copysignf(a, c) : 0.f;
}
__device__ __forceinline__ void hadd(unsigned* h, unsigned bin) {
  unsigned mk = __match_any_sync(__activemask(), bin);
  int lane = threadIdx.x & 31;
  if ((__ffs(mk) - 1) == lane) atomicAdd(&h[bin], (unsigned)__popc(mk));
}

template<int NT, int K>
__device__ void select_bin(const unsigned* hist, unsigned rank,
                           unsigned* s_bin, unsigned* s_rem) {
  __shared__ unsigned wtot[NT/32];
  int tid = threadIdx.x, lane = tid & 31, wid = tid >> 5;
  unsigned tsum = 0;
  #pragma unroll
  for (int k = 0; k < K; k++) tsum += hist[tid*K + k];
  unsigned v = tsum;
  #pragma unroll
  for (int o = 1; o < 32; o <<= 1) {
    unsigned n = __shfl_up_sync(0xffffffffu, v, o);
    if (lane >= o) v += n;
  }
  if (lane == 31) wtot[wid] = v;
  __syncthreads();
  if (tid == 0) {
    unsigned s = 0;
    for (int w = 0; w < NT/32; w++) { unsigned t = wtot[w]; wtot[w] = s; s += t; }
  }
  __syncthreads();
  unsigned incl = v + wtot[wid];
  unsigned excl = incl - tsum;
  if (rank >= excl && rank < incl) {
    unsigned c = excl;
    #pragma unroll
    for (int k = 0; k < K; k++) {
      unsigned hb = hist[tid*K + k];
      if (rank < c + hb) { *s_bin = (unsigned)(tid*K + k); *s_rem = rank - c; break; }
      c += hb;
    }
  }
  __syncthreads();
}

// ---- A: row DWT (along W), 2 rows/block, 3 channels; fused hist zeroing ----
__global__ void __launch_bounds__(256) k_fwd_rows(const float* __restrict__ x) {
  __shared__ float s[2][1728];
  // fused zeroing of median scratch (consumed by later launches)
  {
    int bid = blockIdx.y*gridDim.x + blockIdx.x;
    int gz = bid*256 + threadIdx.x;
    if (gz < NM*2048) { g_hist0[gz] = 0u; g_hist1[gz] = 0u; }
    if (gz < NM) g_ccnt[gz] = 0u;
  }
  int h0 = blockIdx.x*2, b = blockIdx.y;
  const float4* row4 = (const float4*)(x + (size_t)(b*NH + h0)*NW*3);
  for (int i = threadIdx.x; i < 768; i += 256) {
    float4 v = row4[i];
    int rr = i / 384, lin = 4*(i - 384*rr);
    #pragma unroll
    for (int e = 0; e < 4; e++) {
      int l = lin + e, c = l % 3, w = l / 3;
      s[rr][c*576 + w + (w >> 3)] = (&v.x)[e];
    }
  }
  __syncthreads();
  for (int t = threadIdx.x; t < 396; t += 256) {
    int rr = t / 198, t2 = t - 198*rr;
    int c = t2 / 66, g = t2 - 66*c;
    const float* sc = s[rr] + c*576;
    float samp[22];
    int q0 = 8*g - 14;
    #pragma unroll
    for (int k = 0; k < 22; k++) { int q = refl(q0 + k, NW); samp[k] = sc[q + (q >> 3)]; }
    float a[4], d[4];
    #pragma unroll
    for (int r = 0; r < 4; r++) {
      float av = 0.f, dv = 0.f;
      #pragma unroll
      for (int i = 0; i < 16; i++) {
        float v = samp[2*r + i];
        av += RL[i] * v;
        dv += ((i & 1) ? -RL[15-i] : RL[15-i]) * v;
      }
      a[r] = av; d[r] = dv;
    }
    size_t base = ((size_t)(b*3 + c)*NH + h0 + rr)*SW + 4*g;
    *(float4*)(g_lo + base) = make_float4(a[0],a[1],a[2],a[3]);
    *(float4*)(g_hi + base) = make_float4(d[0],d[1],d[2],d[3]);
  }
}

// ---- B: column DWT split-H -> subbands [m][jh][w] + fused pass-0 hist ------
__global__ void __launch_bounds__(256) k_fwd_cols() {
  __shared__ float s2[32*151];
  __shared__ unsigned hist[2048];
  int bx = blockIdx.x, wt = bx % 9, jc = bx / 9;
  int m = blockIdx.y, z = blockIdx.z;
  int w0 = wt*32, g0 = 17*jc;
  int ge = min(g0 + 16, 65);
  int lo_q = 8*g0 - 14;
  int nrows = 8*(ge - g0) + 22;
  const float* in = (z ? g_hi : g_lo) + (size_t)m*NH*SW;
  float* outA = (z ? g_hl : g_ll) + (size_t)m*SW*SW;
  float* outD = (z ? g_hh : g_lh) + (size_t)m*SW*SW;
  for (int i = threadIdx.x; i < 2048; i += 256) hist[i] = 0u;
  for (int idx = threadIdx.x; idx < 32*nrows; idx += 256) {
    int wl = idx & 31, rr = idx >> 5, w = w0 + wl;
    int q = refl(lo_q + rr, NH);
    s2[wl*151 + rr] = (w < NCo) ? in[(size_t)q*SW + w] : 0.f;
  }
  __syncthreads();
  int lane = threadIdx.x & 31, warp = threadIdx.x >> 5;
  int w = w0 + lane;
  const float* col = s2 + lane*151;
  for (int g = g0 + warp; g <= ge; g += 8) {
    int off = 8*(g - g0);
    float samp[22];
    #pragma unroll
    for (int k = 0; k < 22; k++) samp[k] = col[off + k];
    float a[4], d[4];
    #pragma unroll
    for (int r = 0; r < 4; r++) {
      float av = 0.f, dv = 0.f;
      #pragma unroll
      for (int i = 0; i < 16; i++) {
        float v = samp[2*r + i];
        av += RL[i] * v;
        dv += ((i & 1) ? -RL[15-i] : RL[15-i]) * v;
      }
      a[r] = av; d[r] = dv;
    }
    if (g == 65) { a[3] = 0.f; d[3] = 0.f; } // jh==263 pad row
    if (w < SW) {
      #pragma unroll
      for (int r = 0; r < 4; r++) {
        int jh = 4*g + r;
        outA[(size_t)jh*SW + w] = a[r];
        outD[(size_t)jh*SW + w] = d[r];
        hadd(hist, __float_as_uint(fabsf(d[r])) >> 21);
        if (z) hadd(hist, __float_as_uint(fabsf(a[r])) >> 21);
      }
    }
  }
  __syncthreads();
  for (int i = threadIdx.x; i < 2048; i += 256)
    if (hist[i]) atomicAdd(&g_hist0[m*2048 + i], hist[i]);
}

// ---- M2: redundant pass-0 select + refine hist + compact matching keys -----
__global__ void __launch_bounds__(256) k_pass1() {
  __shared__ unsigned hist[2048];
  __shared__ unsigned s_bin, s_rem;
  int cx = blockIdx.x, m = blockIdx.y, band = blockIdx.z;
  select_bin<256, 8>(g_hist0 + m*2048, RANKSEL, &s_bin, &s_rem);
  unsigned pref0 = s_bin;
  if (cx == 0 && band == 0 && threadIdx.x == 0) {
    g_pref0[m] = s_bin; g_rank1[m] = s_rem;
  }
  const float* bp = (band == 0 ? g_lh : (band == 1 ? g_hl : g_hh)) + (size_t)m*SW*SW;
  const float4* p = (const float4*)bp;
  for (int i = threadIdx.x; i < 2048; i += 256) hist[i] = 0u;
  __syncthreads();
  int lo = cx*2178, hi = lo + 2178;
  int lane = threadIdx.x & 31;
  for (int base = lo; base < hi; base += 256) {
    int i = base + threadIdx.x;
    float4 v = make_float4(0.f, 0.f, 0.f, 0.f);
    if (i < hi) v = p[i];
    #pragma unroll
    for (int e = 0; e < 4; e++) {
      unsigned key = __float_as_uint(fabsf((&v.x)[e]));
      bool ok = (i < hi) && ((key >> 21) == pref0);
      unsigned mk = __ballot_sync(0xffffffffu, ok);
      if (mk) {
        int leader = __ffs(mk) - 1;
        unsigned basec = 0;
        if (lane == leader) basec = atomicAdd(&g_ccnt[m], (unsigned)__popc(mk));
        basec = __shfl_sync(0xffffffffu, basec, leader);
        if (ok) {
          atomicAdd(&hist[(key >> 10) & 2047u], 1u);
          g_cand[(size_t)m*CAP + basec + __popc(mk & ((1u << lane) - 1u))] = key;
        }
      }
    }
  }
  __syncthreads();
  for (int i = threadIdx.x; i < 2048; i += 256)
    if (hist[i]) atomicAdd(&g_hist1[m*2048 + i], hist[i]);
}

// ---- M3: finish on candidates -> threshold ---------------------------------
__global__ void __launch_bounds__(512) k_final() {
  int m = blockIdx.x;
  __shared__ unsigned sh[2048];
  __shared__ unsigned s_bin, s_rem;
  for (int i = threadIdx.x; i < 2048; i += 512) sh[i] = g_hist1[m*2048 + i];
  __syncthreads();
  select_bin<512, 4>(sh, g_rank1[m], &s_bin, &s_rem);
  unsigned pref01 = (g_pref0[m] << 11) | s_bin;
  unsigned r2 = s_rem;
  __syncthreads();
  for (int i = threadIdx.x; i < 1024; i += 512) sh[i] = 0u;
  __syncthreads();
  unsigned cnt = g_ccnt[m];
  const unsigned* cand = g_cand + (size_t)m*CAP;
  for (unsigned i = threadIdx.x; i < cnt; i += 512) {
    unsigned key = cand[i];
    if ((key >> 10) == pref01) atomicAdd(&sh[key & 1023u], 1u);
  }
  __syncthreads();
  select_bin<512, 2>(sh, r2, &s_bin, &s_rem);
  if (threadIdx.x == 0) {
    unsigned key = (pref01 << 10) | s_bin;
    double med = (double)__uint_as_float(key);
    g_thr[m] = (float)(med / 0.6745 * sqrt(2.0 * log(262144.0)));
  }
}

// ---- C: inverse column DWT (subbands [jh][w]), soft fused ------------------
__global__ void __launch_bounds__(256) k_inv_cols() {
  __shared__ float ca[32*71], cd[32*71];
  int bx = blockIdx.x, wt = bx % 9, jc = bx / 9;
  int m = blockIdx.y, z = blockIdx.z;
  int w0 = wt*32, gc0 = 16*jc, p_lo = 64*jc;
  const float* A = (z ? g_hl : g_ll) + (size_t)m*SW*SW;
  const float* D = (z ? g_hh : g_lh) + (size_t)m*SW*SW;
  float* out = (z ? g_hi : g_lo) + (size_t)m*NH*SW;
  float thr = g_thr[m];
  for (int idx = threadIdx.x; idx < 32*71; idx += 256) {
    int wl = idx & 31, rr = idx >> 5;
    int w = w0 + wl, p = p_lo + rr;
    float va = 0.f, vd = 0.f;
    if (w < NCo) { va = A[(size_t)p*SW + w]; vd = D[(size_t)p*SW + w]; }
    if (z) va = softf(va, thr);
    vd = softf(vd, thr);
    ca[wl*71 + rr] = va;
    cd[wl*71 + rr] = vd;
  }
  __syncthreads();
  int lane = threadIdx.x & 31, warp = threadIdx.x >> 5;
  int w = w0 + lane;
  bool wok = (w < NCo);
  const float* cap = ca + lane*71;
  const float* cdp = cd + lane*71;
  for (int gl = warp; gl < 16; gl += 8) {
    int gc = gc0 + gl, pr = 4*gl;
    float ac[11], dc[11];
    #pragma unroll
    for (int k = 0; k < 11; k++) { ac[k] = cap[pr + k]; dc[k] = cdp[pr + k]; }
    #pragma unroll
    for (int r = 0; r < 4; r++) {
      float y0 = 0.f, y1 = 0.f;
      #pragma unroll
      for (int u = 0; u < 8; u++) {
        float va = ac[r + 7 - u], vd = dc[r + 7 - u];
        y0 += va * RL[2*u]     + vd * RL[15 - 2*u];
        y1 += va * RL[2*u + 1] - vd * RL[14 - 2*u];
      }
      if (wok) {
        int i0 = 8*gc + 2*r;
        out[(size_t)i0*SW + w]     = y0;
        out[(size_t)(i0+1)*SW + w] = y1;
      }
    }
  }
}

// ---- D: inverse row DWT + NHWC interleave, 2 rows/block --------------------
__global__ void __launch_bounds__(256) k_inv_rows(float* __restrict__ out) {
  __shared__ float ca[2][888], cd[2][888], rowbuf[2][1536];
  int h0 = blockIdx.x*2, b = blockIdx.y;
  for (int i = threadIdx.x; i < 396; i += 256) {
    int rr = i / 198, t2 = i - 198*rr;
    int c = t2 / 66, f = t2 - 66*c;
    const float4* rl4 = (const float4*)(g_lo + ((size_t)(b*3 + c)*NH + h0 + rr)*SW);
    const float4* rh4 = (const float4*)(g_hi + ((size_t)(b*3 + c)*NH + h0 + rr)*SW);
    float4 va = rl4[f], vd = rh4[f];
    int a0 = c*296 + 4*f + (f >> 1);
    #pragma unroll
    for (int e = 0; e < 4; e++) { ca[rr][a0 + e] = (&va.x)[e]; cd[rr][a0 + e] = (&vd.x)[e]; }
  }
  __syncthreads();
  for (int t = threadIdx.x; t < 384; t += 256) {
    int rr = t / 192, rem = t - 192*rr;
    int c = rem >> 6, gc = rem & 63, p0 = 4*gc;
    float ac[11], dc[11];
    #pragma unroll
    for (int k = 0; k < 11; k++) {
      int p = p0 + k, a = c*296 + p + (p >> 3);
      ac[k] = ca[rr][a]; dc[k] = cd[rr][a];
    }
    #pragma unroll
    for (int r = 0; r < 4; r++) {
      float y0 = 0.f, y1 = 0.f;
      #pragma unroll
      for (int u = 0; u < 8; u++) {
        float va = ac[r + 7 - u], vd = dc[r + 7 - u];
        y0 += va * RL[2*u]     + vd * RL[15 - 2*u];
        y1 += va * RL[2*u + 1] - vd * RL[14 - 2*u];
      }
      int o = 2*(p0 + r);
      rowbuf[rr][o*3 + c]       = y0;
      rowbuf[rr][(o + 1)*3 + c] = y1;
    }
  }
  __syncthreads();
  float4* orow = (float4*)(out + (size_t)(b*NH + h0)*NW*3);
  const float4* rb = (const float4*)rowbuf;
  for (int i = threadIdx.x; i < 768; i += 256) orow[i] = rb[i];
}

extern "C" void kernel_launch(void* const* d_in, const int* in_sizes, int n_in,
                              void* d_out, int out_size) {
  const float* x = (const float*)d_in[0];
  float* out = (float*)d_out;
  k_fwd_rows<<<dim3(NH/2, NB), 256>>>(x);
  k_fwd_cols<<<dim3(36, NM, 2), 256>>>();
  k_pass1<<<dim3(8, NM, 3), 256>>>();
  k_final<<<NM, 512>>>();
  k_inv_cols<<<dim3(36, NM, 2), 256>>>();
  k_inv_rows<<<dim3(NH/2, NB), 256>>>(out);
}